// round 15
// baseline (speedup 1.0000x reference)
#include <cuda_runtime.h>
#include <cuda_fp16.h>

#define TT  30
#define TD  150
#define DIM 512
#define MAX_ROWS 34836   // WORDS_CNT + 1
#define NCONV 592        // convert CTAs (4/SM, all wave-1 resident)

// fp16 table + sync state (zero-init .bss, no allocation)
__device__ __half g_w2v_h[(size_t)MAX_ROWS * DIM];
__device__ int    g_cnt[2];           // convert completion counters per half
__device__ int    g_flag[2][1024];    // replicated ready-flags (32 used lines, 128B apart)
__device__ int    g_done;             // gather completion counter (for reset)

// ---- pass 1: fp32 -> fp16, COLUMN-HALF MAJOR --------------------------------
// Each CTA owns a contiguous row band. Converts half 0 (bytes [0,1024) fp32 ->
// [0,512) fp16) of its band, signals; then half 1. Gather half-0 CTAs can
// start as soon as g_flag[0] is up (~half the convert time).
__global__ __launch_bounds__(256)
void w2v_convert_kernel(const float4* __restrict__ src, uint2* __restrict__ dst, int rows)
{
    cudaTriggerProgrammaticLaunchCompletion();   // let gather launch & stage now

    const int nr  = (rows + NCONV - 1) / NCONV;
    const int r0  = blockIdx.x * nr;
    const int rN  = min(nr, rows - r0);          // rows in this band (may be <=0)
    const int tid = threadIdx.x;

    #pragma unroll
    for (int h = 0; h < 2; h++) {
        if (rN > 0) {
            const int tot = rN * 64;             // 64 float4 per half-row
            #pragma unroll 4
            for (int idx = tid; idx < tot; idx += 256) {
                const int row = r0 + (idx >> 6);
                const int c   = idx & 63;
                const int off = row * 128 + h * 64 + c;
                float4 f = __ldcs(&src[off]);
                __half2 a = __floats2half2_rn(f.x, f.y);
                __half2 b = __floats2half2_rn(f.z, f.w);
                uint2 u;
                u.x = *reinterpret_cast<unsigned*>(&a);
                u.y = *reinterpret_cast<unsigned*>(&b);
                dst[off] = u;
            }
        }
        __threadfence();          // release this CTA's stores for half h
        __syncthreads();
        if (tid == 0) {
            int old = atomicAdd(&g_cnt[h], 1);
            if (old == NCONV - 1) {              // last arriver: broadcast flag
                #pragma unroll
                for (int k = 0; k < 32; k++)
                    atomicExch(&g_flag[h][k << 5], 1);
            }
        }
    }
}

// ---- pass 2: gather + pool (R9 body; spin-flag instead of grid sync) --------
// CTA order (earliest-ready, longest-work first):
//   [0,B): desc half0   [B,2B): title half0   [2B,3B): desc half1   [3B,4B): title half1
__global__ __launch_bounds__(32)
void swem_cat_kernel(const void* __restrict__ title_v,
                     const void* __restrict__ desc_v,
                     const void* __restrict__ tlen_v,
                     const void* __restrict__ dlen_v,
                     float* __restrict__ out,
                     int B)
{
    __shared__ int s_off[TD];     // pre-scaled byte offsets (idx * 1024)
    __shared__ int s_len;
    __shared__ int s_is64;

    const int cta = blockIdx.x;
    const int tid = threadIdx.x;
    const int q   = cta / B;            // 0..3
    const int b   = cta - q * B;
    const bool isDesc = (q & 1) == 0;
    const int half    = q >> 1;
    const int nTok    = isDesc ? TD : TT;

    // dtype detection: int64 vs int32 indices (values < 34836 => high word 0)
    {
        unsigned hi  = ((const unsigned*)title_v)[2 * tid + 1];
        unsigned any = __ballot_sync(0xffffffffu, hi != 0u);
        if (tid == 0) s_is64 = (any == 0u) ? 1 : 0;
    }
    __syncthreads();

    const void* idx_v = isDesc ? desc_v : title_v;
    const void* len_v = isDesc ? dlen_v : tlen_v;

    if (s_is64) {
        const long long* ip = (const long long*)idx_v + (long long)b * nTok;
        for (int i = tid; i < nTok; i += 32) s_off[i] = ((int)ip[i]) << 10;
        if (tid == 0) s_len = (int)((const long long*)len_v)[b];
    } else {
        const int* ip = (const int*)idx_v + b * nTok;
        for (int i = tid; i < nTok; i += 32) s_off[i] = ip[i] << 10;
        if (tid == 0) s_len = ((const int*)len_v)[b];
    }
    __syncthreads();

    // Wait for OUR column-half of the fp16 table (replicated flag, light spin).
    if (tid == 0) {
        volatile int* f = &g_flag[half][(cta & 31) << 5];
        while (*f == 0) __nanosleep(512);
    }
    __syncwarp();
    __threadfence();   // acquire: order table reads after observed flag

    const int len = s_len;
    // this CTA covers dims [half*256, half*256+256); thread slice = 8 dims
    const char* hbase = (const char*)g_w2v_h + half * 512 + tid * 16;
    float* orow = out + (size_t)b * (4 * DIM) + (isDesc ? DIM : 0)
                      + half * 256 + tid * 8;

    const __half2 NEGH2 = __halves2half2(__ushort_as_half(0xFC00),
                                         __ushort_as_half(0xFC00)); // (-inf,-inf)

    __half2 mx0 = NEGH2, mx1 = NEGH2, mx2 = NEGH2, mx3 = NEGH2;
    float sm0=0.f, sm1=0.f, sm2=0.f, sm3=0.f, sm4=0.f, sm5=0.f, sm6=0.f, sm7=0.f;

    int t = 0;
    #pragma unroll 4
    for (; t + 1 < len; t += 2) {
        const uint4 ua = *(const uint4*)(hbase + s_off[t]);
        const uint4 ub = *(const uint4*)(hbase + s_off[t + 1]);
        const __half2 a0 = *(const __half2*)&ua.x, a1 = *(const __half2*)&ua.y;
        const __half2 a2 = *(const __half2*)&ua.z, a3 = *(const __half2*)&ua.w;
        const __half2 b0 = *(const __half2*)&ub.x, b1 = *(const __half2*)&ub.y;
        const __half2 b2 = *(const __half2*)&ub.z, b3 = *(const __half2*)&ub.w;
        mx0 = __hmax2(mx0, __hmax2(a0, b0));
        mx1 = __hmax2(mx1, __hmax2(a1, b1));
        mx2 = __hmax2(mx2, __hmax2(a2, b2));
        mx3 = __hmax2(mx3, __hmax2(a3, b3));
        const __half2 p0 = __hadd2(a0, b0), p1 = __hadd2(a1, b1);
        const __half2 p2 = __hadd2(a2, b2), p3 = __hadd2(a3, b3);
        float2 f;
        f = __half22float2(p0); sm0 += f.x; sm1 += f.y;
        f = __half22float2(p1); sm2 += f.x; sm3 += f.y;
        f = __half22float2(p2); sm4 += f.x; sm5 += f.y;
        f = __half22float2(p3); sm6 += f.x; sm7 += f.y;
    }
    if (t < len) {   // odd tail token
        const uint4 u = *(const uint4*)(hbase + s_off[t]);
        const __half2 h0 = *(const __half2*)&u.x, h1 = *(const __half2*)&u.y;
        const __half2 h2 = *(const __half2*)&u.z, h3 = *(const __half2*)&u.w;
        mx0 = __hmax2(mx0, h0); mx1 = __hmax2(mx1, h1);
        mx2 = __hmax2(mx2, h2); mx3 = __hmax2(mx3, h3);
        float2 f;
        f = __half22float2(h0); sm0 += f.x; sm1 += f.y;
        f = __half22float2(h1); sm2 += f.x; sm3 += f.y;
        f = __half22float2(h2); sm4 += f.x; sm5 += f.y;
        f = __half22float2(h3); sm6 += f.x; sm7 += f.y;
    }

    float4 mxa, mxb, ava, avb;
    if (len > 0) {
        float2 m0 = __half22float2(mx0), m1 = __half22float2(mx1);
        float2 m2 = __half22float2(mx2), m3 = __half22float2(mx3);
        mxa = make_float4(m0.x, m0.y, m1.x, m1.y);
        mxb = make_float4(m2.x, m2.y, m3.x, m3.y);
        const float inv = 1.0f / (float)len;
        ava = make_float4(sm0 * inv, sm1 * inv, sm2 * inv, sm3 * inv);
        avb = make_float4(sm4 * inv, sm5 * inv, sm6 * inv, sm7 * inv);
    } else {
        mxa = mxb = ava = avb = make_float4(0.f, 0.f, 0.f, 0.f);
    }
    *(float4*)(orow)               = mxa;   // max quadrant
    *(float4*)(orow + 4)           = mxb;
    *(float4*)(orow + 2 * DIM)     = ava;   // avg quadrant (+2*DIM from max)
    *(float4*)(orow + 2 * DIM + 4) = avb;

    // last gather CTA resets sync state for the next graph replay
    if (tid == 0) {
        int old = atomicAdd(&g_done, 1);
        if (old == 4 * B - 1) {
            atomicExch(&g_cnt[0], 0);
            atomicExch(&g_cnt[1], 0);
            #pragma unroll
            for (int k = 0; k < 32; k++) {
                atomicExch(&g_flag[0][k << 5], 0);
                atomicExch(&g_flag[1][k << 5], 0);
            }
            atomicExch(&g_done, 0);
        }
    }
}

extern "C" void kernel_launch(void* const* d_in, const int* in_sizes, int n_in,
                              void* d_out, int out_size)
{
    const void* title = d_in[0];
    const void* desc  = d_in[1];
    const void* tlen  = d_in[2];
    const void* dlen  = d_in[3];
    const float* w2v  = (const float*)d_in[n_in - 1];
    float* out        = (float*)d_out;

    const int B = in_sizes[2];                        // t_len has B elements

    long long w2v_elems = in_sizes[n_in - 1];
    long long rows = w2v_elems / DIM;
    if (rows > MAX_ROWS) rows = MAX_ROWS;

    __half* dsth;
    cudaGetSymbolAddress((void**)&dsth, g_w2v_h);     // address only, no alloc

    // primary: half-major conversion (PDL trigger at entry)
    w2v_convert_kernel<<<NCONV, 256>>>((const float4*)w2v, (uint2*)dsth, (int)rows);

    // secondary: gather, PDL so it launches immediately and spins on per-half flags
    cudaLaunchConfig_t cfg = {};
    cfg.gridDim  = dim3(4 * B, 1, 1);
    cfg.blockDim = dim3(32, 1, 1);
    cudaLaunchAttribute attr[1];
    attr[0].id = cudaLaunchAttributeProgrammaticStreamSerialization;
    attr[0].val.programmaticStreamSerializationAllowed = 1;
    cfg.attrs = attr;
    cfg.numAttrs = 1;
    cudaLaunchKernelEx(&cfg, swem_cat_kernel, title, desc, tlen, dlen, out, B);
}

// round 16
// speedup vs baseline: 1.2382x; 1.2382x over previous
#include <cuda_runtime.h>
#include <cuda_fp16.h>

#define TT  30
#define TD  150
#define DIM 512
#define MAX_ROWS 34836   // WORDS_CNT + 1

// fp16 copy of the embedding table (zero-init .bss, no allocation)
__device__ __half g_w2v_h[(size_t)MAX_ROWS * DIM];

// ---- pass 1: fp32 -> fp16 table conversion ----------------------------------
// fp32 reads: DEFAULT policy (normal priority) so the 71 MB table becomes and
// stays L2-resident across graph replays (it is the only normal-priority
// allocation in the whole pipeline). fp16 stores: __stcs evict-first.
__global__ __launch_bounds__(256)
void w2v_convert_kernel(const float4* __restrict__ src, uint2* __restrict__ dst, int n4)
{
    const int stride = gridDim.x * 256;
    int i = blockIdx.x * 256 + threadIdx.x;

    for (; i + 7 * stride < n4; i += 8 * stride) {
        float4 f[8];
        #pragma unroll
        for (int k = 0; k < 8; k++) f[k] = src[i + k * stride];   // normal priority
        #pragma unroll
        for (int k = 0; k < 8; k++) {
            __half2 a = __floats2half2_rn(f[k].x, f[k].y);
            __half2 b = __floats2half2_rn(f[k].z, f[k].w);
            uint2 u;
            u.x = *reinterpret_cast<unsigned*>(&a);
            u.y = *reinterpret_cast<unsigned*>(&b);
            __stcs(&dst[i + k * stride], u);                      // evict-first
        }
    }
    for (; i < n4; i += stride) {
        float4 f = src[i];
        __half2 a = __floats2half2_rn(f.x, f.y), b = __floats2half2_rn(f.z, f.w);
        uint2 u; u.x = *(unsigned*)&a; u.y = *(unsigned*)&b;
        __stcs(&dst[i], u);
    }
}

// ---- pass 2: gather + pool (R9 structure — measured 19.4 us) -----------------
// Fine-grained: 32-thread CTAs, each CTA = (pool, row, dim-half).
//   CTAs [0, 2B)  : DESC (long work scheduled first);  CTAs [2B, 4B) : TITLE.
// Thread owns 8 dims (one LDG.128 per token). Max via hmax2 (exact),
// sums via fp16 pair-add then fp32 accumulate. No cross-thread merging.
// ALL loads/stores evict-first so they never displace the resident fp32 table.
__global__ __launch_bounds__(32)
void swem_cat_kernel(const void* __restrict__ title_v,
                     const void* __restrict__ desc_v,
                     const void* __restrict__ tlen_v,
                     const void* __restrict__ dlen_v,
                     float* __restrict__ out,
                     int B)
{
    __shared__ int s_off[TD];     // pre-scaled byte offsets (idx * 1024)
    __shared__ int s_len;
    __shared__ int s_is64;

    const int cta = blockIdx.x;
    const int tid = threadIdx.x;
    const bool isDesc = (cta < 2 * B);
    const int local   = isDesc ? cta : (cta - 2 * B);
    const int b       = local >> 1;
    const int half    = local & 1;
    const int nTok    = isDesc ? TD : TT;

    // dtype detection: int64 vs int32 indices (values < 34836 => high word 0)
    {
        unsigned hi  = __ldcs(&((const unsigned*)title_v)[2 * tid + 1]);
        unsigned any = __ballot_sync(0xffffffffu, hi != 0u);
        if (tid == 0) s_is64 = (any == 0u) ? 1 : 0;
    }
    __syncthreads();

    const void* idx_v = isDesc ? desc_v : title_v;
    const void* len_v = isDesc ? dlen_v : tlen_v;

    if (s_is64) {
        const long long* ip = (const long long*)idx_v + (long long)b * nTok;
        for (int i = tid; i < nTok; i += 32) s_off[i] = ((int)__ldcs(&ip[i])) << 10;
        if (tid == 0) s_len = (int)__ldcs(&((const long long*)len_v)[b]);
    } else {
        const int* ip = (const int*)idx_v + b * nTok;
        for (int i = tid; i < nTok; i += 32) s_off[i] = __ldcs(&ip[i]) << 10;
        if (tid == 0) s_len = __ldcs(&((const int*)len_v)[b]);
    }
    __syncthreads();

    const int len = s_len;
    // this CTA covers dims [half*256, half*256+256); thread slice = 8 dims
    const char* hbase = (const char*)g_w2v_h + half * 512 + tid * 16;
    float* orow = out + (size_t)b * (4 * DIM) + (isDesc ? DIM : 0)
                      + half * 256 + tid * 8;

    const __half2 NEGH2 = __halves2half2(__ushort_as_half(0xFC00),
                                         __ushort_as_half(0xFC00)); // (-inf,-inf)

    __half2 mx0 = NEGH2, mx1 = NEGH2, mx2 = NEGH2, mx3 = NEGH2;
    float sm0=0.f, sm1=0.f, sm2=0.f, sm3=0.f, sm4=0.f, sm5=0.f, sm6=0.f, sm7=0.f;

    int t = 0;
    #pragma unroll 4
    for (; t + 1 < len; t += 2) {
        const uint4 ua = __ldcs((const uint4*)(hbase + s_off[t]));
        const uint4 ub = __ldcs((const uint4*)(hbase + s_off[t + 1]));
        const __half2 a0 = *(const __half2*)&ua.x, a1 = *(const __half2*)&ua.y;
        const __half2 a2 = *(const __half2*)&ua.z, a3 = *(const __half2*)&ua.w;
        const __half2 b0 = *(const __half2*)&ub.x, b1 = *(const __half2*)&ub.y;
        const __half2 b2 = *(const __half2*)&ub.z, b3 = *(const __half2*)&ub.w;
        mx0 = __hmax2(mx0, __hmax2(a0, b0));
        mx1 = __hmax2(mx1, __hmax2(a1, b1));
        mx2 = __hmax2(mx2, __hmax2(a2, b2));
        mx3 = __hmax2(mx3, __hmax2(a3, b3));
        const __half2 p0 = __hadd2(a0, b0), p1 = __hadd2(a1, b1);
        const __half2 p2 = __hadd2(a2, b2), p3 = __hadd2(a3, b3);
        float2 f;
        f = __half22float2(p0); sm0 += f.x; sm1 += f.y;
        f = __half22float2(p1); sm2 += f.x; sm3 += f.y;
        f = __half22float2(p2); sm4 += f.x; sm5 += f.y;
        f = __half22float2(p3); sm6 += f.x; sm7 += f.y;
    }
    if (t < len) {   // odd tail token
        const uint4 u = __ldcs((const uint4*)(hbase + s_off[t]));
        const __half2 h0 = *(const __half2*)&u.x, h1 = *(const __half2*)&u.y;
        const __half2 h2 = *(const __half2*)&u.z, h3 = *(const __half2*)&u.w;
        mx0 = __hmax2(mx0, h0); mx1 = __hmax2(mx1, h1);
        mx2 = __hmax2(mx2, h2); mx3 = __hmax2(mx3, h3);
        float2 f;
        f = __half22float2(h0); sm0 += f.x; sm1 += f.y;
        f = __half22float2(h1); sm2 += f.x; sm3 += f.y;
        f = __half22float2(h2); sm4 += f.x; sm5 += f.y;
        f = __half22float2(h3); sm6 += f.x; sm7 += f.y;
    }

    float4 mxa, mxb, ava, avb;
    if (len > 0) {
        float2 m0 = __half22float2(mx0), m1 = __half22float2(mx1);
        float2 m2 = __half22float2(mx2), m3 = __half22float2(mx3);
        mxa = make_float4(m0.x, m0.y, m1.x, m1.y);
        mxb = make_float4(m2.x, m2.y, m3.x, m3.y);
        const float inv = 1.0f / (float)len;
        ava = make_float4(sm0 * inv, sm1 * inv, sm2 * inv, sm3 * inv);
        avb = make_float4(sm4 * inv, sm5 * inv, sm6 * inv, sm7 * inv);
    } else {
        mxa = mxb = ava = avb = make_float4(0.f, 0.f, 0.f, 0.f);
    }
    __stcs((float4*)(orow),               mxa);   // max quadrant (evict-first)
    __stcs((float4*)(orow + 4),           mxb);
    __stcs((float4*)(orow + 2 * DIM),     ava);   // avg quadrant
    __stcs((float4*)(orow + 2 * DIM + 4), avb);
}

extern "C" void kernel_launch(void* const* d_in, const int* in_sizes, int n_in,
                              void* d_out, int out_size)
{
    const void* title = d_in[0];
    const void* desc  = d_in[1];
    const void* tlen  = d_in[2];
    const void* dlen  = d_in[3];
    const float* w2v  = (const float*)d_in[n_in - 1];
    float* out        = (float*)d_out;

    const int B = in_sizes[2];                        // t_len has B elements

    long long w2v_elems = in_sizes[n_in - 1];
    long long rows = w2v_elems / DIM;
    if (rows > MAX_ROWS) rows = MAX_ROWS;
    const int n4 = (int)(rows * (DIM / 4));           // float4 chunks

    __half* dsth;
    cudaGetSymbolAddress((void**)&dsth, g_w2v_h);     // address only, no alloc

    w2v_convert_kernel<<<1184, 256>>>((const float4*)w2v, (uint2*)dsth, n4);
    swem_cat_kernel<<<4 * B, 32>>>(title, desc, tlen, dlen, out, B);
}